// round 10
// baseline (speedup 1.0000x reference)
#include <cuda_runtime.h>
#include <math.h>

// Problem constants
#define BB 16
#define LL 2048
#define DM 512
#define FF 1025       // LL/2 + 1
#define FFP 1152      // padded F; pads stay zero (zero-init, never written)
#define HH 8
#define EE 64
#define OO 512        // HH*EE
#define NFFT 2048
#define KP 1024       // proj interleaved K = 2*DM

// ---------------- device scratch (static globals; zero-initialized) ----------------
__device__ float g_tr[(size_t)BB * DM * LL];                  // transpose scratch
__device__ float g_spec[3][(size_t)BB * KP * FFP];            // interleaved re/im rows (b, 2c+p, f)
__device__ float g_Wt[3][(size_t)KP * OO];                    // interleaved weights [k][o]
__device__ float g_w2[3][OO];
__device__ float g_qkT[2][(size_t)BB * OO * FFP];             // q,k heads (b, o, f)
__device__ float g_v[(size_t)BB * HH * FFP * EE];             // v heads (b,h,f,e)
__device__ float g_ctx[(size_t)BB * FFP * OO];                // (b, f, h*e)
__device__ float g_scores[(size_t)BB * HH * FF * FF];         // attn fallback
__device__ float g_yre[(size_t)BB * DM * FF];
__device__ float g_yim[(size_t)BB * DM * FF];

// ---------------- f32x2 packed helpers ----------------
__device__ __forceinline__ unsigned long long pk2(float x, float y) {
    unsigned long long r;
    asm("mov.b64 %0, {%1, %2};" : "=l"(r) : "f"(x), "f"(y));
    return r;
}
__device__ __forceinline__ void fma2(unsigned long long& d, unsigned long long a,
                                     unsigned long long b) {
    asm("fma.rn.f32x2 %0, %1, %2, %0;" : "+l"(d) : "l"(a), "l"(b));
}
__device__ __forceinline__ void upk2(unsigned long long v, float& x, float& y) {
    asm("mov.b64 {%0, %1}, %2;" : "=f"(x), "=f"(y) : "l"(v));
}

// ---------------- weight prep: interleave W0/W1 rows ----------------
__global__ void prep_w(const float* __restrict__ Wq, const float* __restrict__ Wk,
                       const float* __restrict__ Wv) {
    int idx = blockIdx.x * blockDim.x + threadIdx.x;
    if (idx >= 3 * KP * OO) return;
    int t = idx / (KP * OO);
    int r = idx % (KP * OO);
    int k = r / OO, o = r % OO;
    const float* W = (t == 0) ? Wq : (t == 1) ? Wk : Wv;
    g_Wt[t][(size_t)k * OO + o] = W[(o * DM + (k >> 1)) * 3 + (k & 1)];
}

__global__ void prep_w2(const float* __restrict__ Wq, const float* __restrict__ Wk,
                        const float* __restrict__ Wv) {
    int idx = blockIdx.x * blockDim.x + threadIdx.x;
    if (idx >= 3 * OO) return;
    int t = idx / OO;
    int o = idx % OO;
    const float* W = (t == 0) ? Wq : (t == 1) ? Wk : Wv;
    float s = 0.f;
    for (int c = 0; c < DM; ++c) s += W[(o * DM + c) * 3 + 2];
    g_w2[t][o] = s;
}

// ---------------- transpose (B, Ld, Cd) -> (B, Cd, Ld) ----------------
__global__ void transpose_kernel(const float* __restrict__ in, float* __restrict__ out,
                                 int Ld, int Cd) {
    __shared__ float tile[32][33];
    int b = blockIdx.z;
    int l0 = blockIdx.x * 32, c0 = blockIdx.y * 32;
    int tx = threadIdx.x, ty = threadIdx.y;
    #pragma unroll
    for (int i = 0; i < 32; i += 8) {
        int l = l0 + ty + i, c = c0 + tx;
        if (l < Ld && c < Cd) tile[ty + i][tx] = in[((size_t)b * Ld + l) * Cd + c];
    }
    __syncthreads();
    #pragma unroll
    for (int i = 0; i < 32; i += 8) {
        int c = c0 + ty + i, l = l0 + tx;
        if (c < Cd && l < Ld) out[((size_t)b * Cd + c) * Ld + l] = tile[tx][ty + i];
    }
}

// ---------------- forward rfft: two real channels per complex FFT ----------------
__global__ void rfft_pair(const float* __restrict__ x, int ti) {
    __shared__ float2 s[NFFT];
    int blk = blockIdx.x;
    int b = blk / (DM / 2);
    int p = (blk % (DM / 2)) * 2;
    const float* x0 = x + ((size_t)b * DM + p) * LL;
    int t = threadIdx.x;   // 512 threads
    for (int i = t; i < NFFT; i += 512) {
        int r = __brev((unsigned)i) >> 21;
        s[r] = make_float2(x0[i], x0[i + LL]);
    }
    __syncthreads();
    for (int sh = 0; sh < 11; ++sh) {
        int half = 1 << sh;
        for (int j = t; j < NFFT / 2; j += 512) {
            int pos = j & (half - 1);
            int base = ((j >> sh) << (sh + 1)) | pos;
            float ang = -3.14159265358979f * (float)pos / (float)half;
            float sw, cw; __sincosf(ang, &sw, &cw);
            float2 a = s[base], q2 = s[base + half];
            float tr = cw * q2.x - sw * q2.y;
            float tiy = cw * q2.y + sw * q2.x;
            s[base]        = make_float2(a.x + tr, a.y + tiy);
            s[base + half] = make_float2(a.x - tr, a.y - tiy);
        }
        __syncthreads();
    }
    float* sp = g_spec[ti];
    size_t o0 = ((size_t)b * KP + 2 * p) * FFP;
    for (int f = t; f <= NFFT / 2; f += 512) {
        float2 Zf = s[f];
        float2 Zn = s[(NFFT - f) & (NFFT - 1)];
        sp[o0 + f]            = 0.5f * (Zf.x + Zn.x);   // re ch p
        sp[o0 + FFP + f]      = 0.5f * (Zf.y - Zn.y);   // im ch p
        sp[o0 + 2 * FFP + f]  = 0.5f * (Zf.y + Zn.y);   // re ch p+1
        sp[o0 + 3 * FFP + f]  = 0.5f * (Zn.x - Zf.x);   // im ch p+1
    }
}

// ============ common 128x128 f32x2 inner product (16 k-steps) ============
#define GEMM_INNER_128(As, Bs, acc, ty, tx)                                          \
    _Pragma("unroll")                                                                \
    for (int kk = 0; kk < 16; ++kk) {                                                \
        float4 a0 = *(const float4*)&As[kk][(ty) * 4];                               \
        float4 a1 = *(const float4*)&As[kk][64 + (ty) * 4];                          \
        float4 b0 = *(const float4*)&Bs[kk][(tx) * 4];                               \
        float4 b1 = *(const float4*)&Bs[kk][64 + (tx) * 4];                          \
        unsigned long long bb0 = pk2(b0.x, b0.y), bb1 = pk2(b0.z, b0.w);             \
        unsigned long long bb2 = pk2(b1.x, b1.y), bb3 = pk2(b1.z, b1.w);             \
        float av[8] = {a0.x, a0.y, a0.z, a0.w, a1.x, a1.y, a1.z, a1.w};              \
        _Pragma("unroll")                                                            \
        for (int r = 0; r < 8; ++r) {                                                \
            unsigned long long ad = pk2(av[r], av[r]);                               \
            fma2(acc[r][0], ad, bb0); fma2(acc[r][1], ad, bb1);                      \
            fma2(acc[r][2], ad, bb2); fma2(acc[r][3], ad, bb3);                      \
        }                                                                            \
    }

// ---------------- projection GEMM (f < 1024 tiles) ----------------
__global__ __launch_bounds__(256, 2) void proj_kernel(int ti, const float* __restrict__ bias) {
    __shared__ float As[16][132], Bs[16][132];
    int b = blockIdx.z;
    int f0 = blockIdx.x * 128;
    int n0 = blockIdx.y * 128;
    int tid = threadIdx.x, ty = tid >> 4, tx = tid & 15;
    const float* sp = g_spec[ti];
    const float* Wt = g_Wt[ti];
    unsigned long long acc[8][4];
    #pragma unroll
    for (int r = 0; r < 8; ++r)
        #pragma unroll
        for (int c = 0; c < 4; ++c) acc[r][c] = 0ull;

    for (int k0 = 0; k0 < KP; k0 += 16) {
        #pragma unroll
        for (int r = 0; r < 2; ++r) {
            int idx = tid + r * 256;
            int kk = idx >> 5, pos = (idx & 31) * 4;
            *(float4*)&As[kk][pos] =
                *(const float4*)&sp[((size_t)b * KP + k0 + kk) * FFP + f0 + pos];
            *(float4*)&Bs[kk][pos] =
                *(const float4*)&Wt[(size_t)(k0 + kk) * OO + n0 + pos];
        }
        __syncthreads();
        GEMM_INNER_128(As, Bs, acc, ty, tx);
        __syncthreads();
    }

    float C[8][8];
    #pragma unroll
    for (int r = 0; r < 8; ++r)
        #pragma unroll
        for (int p2 = 0; p2 < 4; ++p2) upk2(acc[r][p2], C[r][p2 * 2], C[r][p2 * 2 + 1]);

    const float* w2 = g_w2[ti];
    #pragma unroll
    for (int r = 0; r < 8; ++r) {
        int f = f0 + ((r < 4) ? ty * 4 + r : 64 + ty * 4 + (r - 4));
        float fr = (float)f * (1.0f / (float)NFFT);
        #pragma unroll
        for (int c = 0; c < 8; ++c) {
            int o = n0 + ((c < 4) ? tx * 4 + c : 64 + tx * 4 + (c - 4));
            float val = C[r][c] + fr * w2[o] + bias[o];
            if (ti < 2) {
                g_qkT[ti][((size_t)b * OO + o) * FFP + f] = val;
            } else {
                int h = o >> 6, e = o & 63;
                g_v[(((size_t)b * HH + h) * FFP + f) * EE + e] = val;
            }
        }
    }
}

// ---------------- proj edge: the single f=1024 column ----------------
__global__ void proj_edge(int ti, const float* __restrict__ bias) {
    __shared__ float sc[KP];
    int b = blockIdx.x, quad = blockIdx.y;
    int t = threadIdx.x;   // 128
    const float* sp = g_spec[ti] + (size_t)b * KP * FFP;
    for (int k = t; k < KP; k += 128) sc[k] = sp[(size_t)k * FFP + 1024];
    __syncthreads();
    int o = quad * 128 + t;
    const float* Wt = g_Wt[ti];
    float a0 = 0.f, a1 = 0.f, a2 = 0.f, a3 = 0.f;
    for (int k = 0; k < KP; k += 4) {
        a0 += sc[k + 0] * Wt[(size_t)(k + 0) * OO + o];
        a1 += sc[k + 1] * Wt[(size_t)(k + 1) * OO + o];
        a2 += sc[k + 2] * Wt[(size_t)(k + 2) * OO + o];
        a3 += sc[k + 3] * Wt[(size_t)(k + 3) * OO + o];
    }
    float val = (a0 + a1) + (a2 + a3) + 0.5f * g_w2[ti][o] + bias[o];  // f/2048 = 0.5
    if (ti < 2) g_qkT[ti][((size_t)b * OO + o) * FFP + 1024] = val;
    else {
        int h = o >> 6, e = o & 63;
        g_v[(((size_t)b * HH + h) * FFP + 1024) * EE + e] = val;
    }
}

// ---------------- scores: S = scale * Q K^T (l,s < 1024 tiles) ----------------
__global__ __launch_bounds__(256, 2) void scores_kernel(float* __restrict__ attn) {
    __shared__ float As[16][132], Bs[16][132];
    int bh = blockIdx.z;
    int l0 = blockIdx.x * 128, s0 = blockIdx.y * 128;
    int tid = threadIdx.x, ty = tid >> 4, tx = tid & 15;
    const float* qb = g_qkT[0] + (size_t)bh * EE * FFP;
    const float* kb = g_qkT[1] + (size_t)bh * EE * FFP;
    unsigned long long acc[8][4];
    #pragma unroll
    for (int r = 0; r < 8; ++r)
        #pragma unroll
        for (int c = 0; c < 4; ++c) acc[r][c] = 0ull;

    for (int k0 = 0; k0 < EE; k0 += 16) {
        #pragma unroll
        for (int r = 0; r < 2; ++r) {
            int idx = tid + r * 256;
            int kk = idx >> 5, pos = (idx & 31) * 4;
            *(float4*)&As[kk][pos] = *(const float4*)&qb[(size_t)(k0 + kk) * FFP + l0 + pos];
            *(float4*)&Bs[kk][pos] = *(const float4*)&kb[(size_t)(k0 + kk) * FFP + s0 + pos];
        }
        __syncthreads();
        GEMM_INNER_128(As, Bs, acc, ty, tx);
        __syncthreads();
    }

    float C[8][8];
    #pragma unroll
    for (int r = 0; r < 8; ++r)
        #pragma unroll
        for (int p2 = 0; p2 < 4; ++p2) upk2(acc[r][p2], C[r][p2 * 2], C[r][p2 * 2 + 1]);

    const float scale = 0.125f;   // 1/sqrt(64)
    // Row stride FF=1025 is odd -> scalar STG only (vector stores would trap).
    #pragma unroll
    for (int r = 0; r < 8; ++r) {
        int l = l0 + ((r < 4) ? ty * 4 + r : 64 + ty * 4 + (r - 4));
        size_t row = ((size_t)bh * FF + l) * FF;
        #pragma unroll
        for (int c = 0; c < 8; ++c) {
            int s = s0 + ((c < 4) ? tx * 4 + c : 64 + tx * 4 + (c - 4));
            attn[row + s] = C[r][c] * scale;
        }
    }
}

// ---------------- scores edge: row l=1024 and column s=1024 ----------------
__global__ void scores_edge(float* __restrict__ attn) {
    __shared__ float qe[64], ke[64];
    int bh = blockIdx.x;
    const float* qb = g_qkT[0] + (size_t)bh * EE * FFP;
    const float* kb = g_qkT[1] + (size_t)bh * EE * FFP;
    int t = threadIdx.x;   // 256
    if (t < 64) { qe[t] = qb[(size_t)t * FFP + 1024]; ke[t] = kb[(size_t)t * FFP + 1024]; }
    __syncthreads();
    const float scale = 0.125f;
    for (int s = t; s < FF; s += 256) {
        float accr = 0.f, accc = 0.f;
        #pragma unroll 8
        for (int e = 0; e < 64; ++e) {
            accr += qe[e] * kb[(size_t)e * FFP + s];   // S[1024][s]
            accc += qb[(size_t)e * FFP + s] * ke[e];   // S[s][1024]
        }
        attn[((size_t)bh * FF + 1024) * FF + s] = accr * scale;
        attn[((size_t)bh * FF + s) * FF + 1024] = accc * scale;
    }
}

// ---------------- softmax over last axis, in place, warp-uniform MUFU skip ----------------
__global__ void softmax_kernel(float* __restrict__ A) {
    __shared__ float red[256];
    size_t row = blockIdx.x;
    float* p = A + row * FF;
    int t = threadIdx.x;
    float v[5];
    float mx = -1e30f;
    #pragma unroll
    for (int i = 0; i < 5; ++i) {
        int idx = t + i * 256;
        v[i] = (idx < FF) ? p[idx] : -1e30f;
        mx = fmaxf(mx, v[i]);
    }
    red[t] = mx; __syncthreads();
    for (int s = 128; s > 0; s >>= 1) {
        if (t < s) red[t] = fmaxf(red[t], red[t + s]);
        __syncthreads();
    }
    mx = red[0];
    __syncthreads();

    bool live = false;
    #pragma unroll
    for (int i = 0; i < 5; ++i) {
        v[i] -= mx;
        live = live || (v[i] > -80.0f);
    }
    float sum = 0.f;
    unsigned wm = __ballot_sync(0xffffffffu, live);
    if (wm != 0u) {
        #pragma unroll
        for (int i = 0; i < 5; ++i) {
            v[i] = __expf(v[i]);
            sum += v[i];
        }
    } else {
        #pragma unroll
        for (int i = 0; i < 5; ++i) v[i] = 0.f;
    }

    red[t] = sum; __syncthreads();
    for (int s = 128; s > 0; s >>= 1) {
        if (t < s) red[t] += red[t + s];
        __syncthreads();
    }
    float inv = 1.0f / red[0];
    #pragma unroll
    for (int i = 0; i < 5; ++i) {
        int idx = t + i * 256;
        if (idx < FF) p[idx] = v[i] * inv;
    }
}

// ---------------- ctx = attn @ V per (b,h); l < 1024 tiles ----------------
__global__ __launch_bounds__(256, 2) void ctx_kernel(const float* __restrict__ attn) {
    __shared__ float As[16][132], Bs[16][68];
    int bh = blockIdx.z;
    int l0 = blockIdx.x * 128;
    int tid = threadIdx.x, ty = tid >> 4, tx = tid & 15;
    const float* vb = g_v + (size_t)bh * FFP * EE;
    const float* Ab = attn + (size_t)bh * FF * FF;
    unsigned long long acc[8][2];
    #pragma unroll
    for (int r = 0; r < 8; ++r) { acc[r][0] = 0ull; acc[r][1] = 0ull; }

    for (int s0 = 0; s0 < 1040; s0 += 16) {
        #pragma unroll
        for (int r = 0; r < 8; ++r) {
            int idx = tid + r * 256;
            int li = idx >> 4, ss = idx & 15;
            int l = l0 + li, s = s0 + ss;
            As[ss][li] = (s < FF) ? Ab[(size_t)l * FF + s] : 0.f;
        }
        {
            int kk = tid >> 4, pos = (tid & 15) * 4;
            *(float4*)&Bs[kk][pos] = *(const float4*)&vb[(size_t)(s0 + kk) * EE + pos];
        }
        __syncthreads();
        #pragma unroll
        for (int kk = 0; kk < 16; ++kk) {
            float4 a0 = *(const float4*)&As[kk][ty * 4];
            float4 a1 = *(const float4*)&As[kk][64 + ty * 4];
            float4 b0 = *(const float4*)&Bs[kk][tx * 4];
            unsigned long long bb0 = pk2(b0.x, b0.y), bb1 = pk2(b0.z, b0.w);
            float av[8] = {a0.x, a0.y, a0.z, a0.w, a1.x, a1.y, a1.z, a1.w};
            #pragma unroll
            for (int r = 0; r < 8; ++r) {
                unsigned long long ad = pk2(av[r], av[r]);
                fma2(acc[r][0], ad, bb0);
                fma2(acc[r][1], ad, bb1);
            }
        }
        __syncthreads();
    }

    int b = bh >> 3, h = bh & 7;
    #pragma unroll
    for (int r = 0; r < 8; ++r) {
        int l = l0 + ((r < 4) ? ty * 4 + r : 64 + ty * 4 + (r - 4));
        float c0, c1, c2, c3;
        upk2(acc[r][0], c0, c1);
        upk2(acc[r][1], c2, c3);
        *(float4*)&g_ctx[((size_t)b * FFP + l) * OO + h * EE + tx * 4] =
            make_float4(c0, c1, c2, c3);
    }
}

// ---------------- ctx edge: the single l=1024 row ----------------
__global__ void ctx_edge(const float* __restrict__ attn) {
    int bh = blockIdx.x;
    int b = bh >> 3, h = bh & 7;
    int e = threadIdx.x;   // 64
    const float* vb = g_v + (size_t)bh * FFP * EE;
    const float* arow = attn + ((size_t)bh * FF + 1024) * FF;
    float a0 = 0.f, a1 = 0.f;
    int s = 0;
    for (; s + 1 < FF; s += 2) {
        a0 += arow[s] * vb[(size_t)s * EE + e];
        a1 += arow[s + 1] * vb[(size_t)(s + 1) * EE + e];
    }
    if (s < FF) a0 += arow[s] * vb[(size_t)s * EE + e];
    g_ctx[((size_t)b * FFP + 1024) * OO + h * EE + e] = a0 + a1;
}

// ---------------- output projection (f < 1024 tiles) ----------------
__global__ __launch_bounds__(256, 2) void outproj_kernel(const float* __restrict__ Wo,
                                                         const float* __restrict__ bo) {
    __shared__ float As[16][132], Bs[16][132];
    int b = blockIdx.z;
    int m0 = blockIdx.x * 128;   // f tile
    int n0 = blockIdx.y * 128;   // output col tile (of 1024)
    int tid = threadIdx.x, ty = tid >> 4, tx = tid & 15;
    unsigned long long acc[8][4];
    #pragma unroll
    for (int r = 0; r < 8; ++r)
        #pragma unroll
        for (int c = 0; c < 4; ++c) acc[r][c] = 0ull;

    for (int c0 = 0; c0 < OO; c0 += 16) {
        int mi = tid >> 1, cg = (tid & 1) * 8;
        {
            const float* src = &g_ctx[((size_t)b * FFP + m0 + mi) * OO + c0 + cg];
            float4 t0 = *(const float4*)&src[0];
            float4 t1 = *(const float4*)&src[4];
            As[cg + 0][mi] = t0.x; As[cg + 1][mi] = t0.y;
            As[cg + 2][mi] = t0.z; As[cg + 3][mi] = t0.w;
            As[cg + 4][mi] = t1.x; As[cg + 5][mi] = t1.y;
            As[cg + 6][mi] = t1.z; As[cg + 7][mi] = t1.w;
        }
        {
            const float* src = &Wo[(size_t)(n0 + mi) * OO + c0 + cg];
            float4 t0 = *(const float4*)&src[0];
            float4 t1 = *(const float4*)&src[4];
            Bs[cg + 0][mi] = t0.x; Bs[cg + 1][mi] = t0.y;
            Bs[cg + 2][mi] = t0.z; Bs[cg + 3][mi] = t0.w;
            Bs[cg + 4][mi] = t1.x; Bs[cg + 5][mi] = t1.y;
            Bs[cg + 6][mi] = t1.z; Bs[cg + 7][mi] = t1.w;
        }
        __syncthreads();
        GEMM_INNER_128(As, Bs, acc, ty, tx);
        __syncthreads();
    }

    float C[8][8];
    #pragma unroll
    for (int r = 0; r < 8; ++r)
        #pragma unroll
        for (int p2 = 0; p2 < 4; ++p2) upk2(acc[r][p2], C[r][p2 * 2], C[r][p2 * 2 + 1]);

    #pragma unroll
    for (int r = 0; r < 8; ++r) {
        int f = m0 + ((r < 4) ? ty * 4 + r : 64 + ty * 4 + (r - 4));
        #pragma unroll
        for (int c = 0; c < 8; ++c) {
            int jj = n0 + ((c < 4) ? tx * 4 + c : 64 + tx * 4 + (c - 4));
            float val = C[r][c] + bo[jj];
            int dd = jj >> 1;
            if (jj & 1) g_yim[((size_t)b * DM + dd) * FF + f] = val;
            else        g_yre[((size_t)b * DM + dd) * FF + f] = val;
        }
    }
}

// ---------------- outproj edge: the single f=1024 column ----------------
__global__ void outproj_edge(const float* __restrict__ Wo, const float* __restrict__ bo) {
    __shared__ float cs[OO];
    int b = blockIdx.x, oct = blockIdx.y;
    int t = threadIdx.x;   // 128
    for (int c = t; c < OO; c += 128) cs[c] = g_ctx[((size_t)b * FFP + 1024) * OO + c];
    __syncthreads();
    int jj = oct * 128 + t;
    const float* wrow = Wo + (size_t)jj * OO;
    float a0 = 0.f, a1 = 0.f, a2 = 0.f, a3 = 0.f;
    for (int c = 0; c < OO; c += 4) {
        a0 += cs[c + 0] * wrow[c + 0];
        a1 += cs[c + 1] * wrow[c + 1];
        a2 += cs[c + 2] * wrow[c + 2];
        a3 += cs[c + 3] * wrow[c + 3];
    }
    float val = (a0 + a1) + (a2 + a3) + bo[jj];
    int dd = jj >> 1;
    if (jj & 1) g_yim[((size_t)b * DM + dd) * FF + 1024] = val;
    else        g_yre[((size_t)b * DM + dd) * FF + 1024] = val;
}

// ---------------- inverse rfft (irfft discards imag of bins 0 and N/2) ----------------
__global__ void irfft_pair(float* __restrict__ xout) {
    __shared__ float2 s[NFFT];
    int blk = blockIdx.x;
    int b = blk / (DM / 2);
    int p = (blk % (DM / 2)) * 2;
    size_t i0 = ((size_t)b * DM + p) * FF;
    int t = threadIdx.x;  // 512
    for (int f = t; f <= NFFT / 2; f += 512) {
        float y0r = g_yre[i0 + f],      y0i = g_yim[i0 + f];
        float y1r = g_yre[i0 + FF + f], y1i = g_yim[i0 + FF + f];
        if (f == 0 || f == NFFT / 2) { y0i = 0.f; y1i = 0.f; }
        int r1 = __brev((unsigned)f) >> 21;
        s[r1] = make_float2(y0r - y1i, y0i + y1r);
        if (f > 0 && f < NFFT / 2) {
            int r2 = __brev((unsigned)(NFFT - f)) >> 21;
            s[r2] = make_float2(y0r + y1i, y1r - y0i);
        }
    }
    __syncthreads();
    for (int sh = 0; sh < 11; ++sh) {
        int half = 1 << sh;
        for (int j = t; j < NFFT / 2; j += 512) {
            int pos = j & (half - 1);
            int base = ((j >> sh) << (sh + 1)) | pos;
            float ang = 3.14159265358979f * (float)pos / (float)half;
            float sw, cw; __sincosf(ang, &sw, &cw);
            float2 a = s[base], q2 = s[base + half];
            float tr = cw * q2.x - sw * q2.y;
            float tiy = cw * q2.y + sw * q2.x;
            s[base]        = make_float2(a.x + tr, a.y + tiy);
            s[base + half] = make_float2(a.x - tr, a.y - tiy);
        }
        __syncthreads();
    }
    const float inv = 1.0f / (float)NFFT;
    size_t o0 = ((size_t)b * DM + p) * LL;
    for (int n = t; n < NFFT; n += 512) {
        xout[o0 + n]      = s[n].x * inv;
        xout[o0 + LL + n] = s[n].y * inv;
    }
}

// ---------------- launch ----------------
extern "C" void kernel_launch(void* const* d_in, const int* in_sizes, int n_in,
                              void* d_out, int out_size) {
    const float* q  = (const float*)d_in[0];
    const float* k  = (const float*)d_in[1];
    const float* v  = (const float*)d_in[2];
    const float* Wq = (const float*)d_in[3];
    const float* bq = (const float*)d_in[4];
    const float* Wk = (const float*)d_in[5];
    const float* bk = (const float*)d_in[6];
    const float* Wv = (const float*)d_in[7];
    const float* bv = (const float*)d_in[8];
    const float* Wo = (const float*)d_in[9];
    const float* bo = (const float*)d_in[10];
    float* out = (float*)d_out;

    const long long OUT_N  = (long long)BB * LL * DM;           // 16,777,216
    const long long ATTN_N = (long long)BB * HH * FF * FF;      // 134,480,000

    float* scores_dev = nullptr;
    cudaGetSymbolAddress((void**)&scores_dev, g_scores);
    float* tr = nullptr;
    cudaGetSymbolAddress((void**)&tr, g_tr);

    float* attn_ptr = scores_dev;
    if ((long long)out_size >= OUT_N + ATTN_N) attn_ptr = out + OUT_N;

    prep_w<<<(3 * KP * OO + 255) / 256, 256>>>(Wq, Wk, Wv);
    prep_w2<<<(3 * OO + 255) / 256, 256>>>(Wq, Wk, Wv);

    dim3 tb(32, 8);
    const float* ins[3]    = {q, k, v};
    const float* biases[3] = {bq, bk, bv};
    for (int ti = 0; ti < 3; ++ti) {
        dim3 tg(LL / 32, DM / 32, BB);
        transpose_kernel<<<tg, tb>>>(ins[ti], tr, LL, DM);
        rfft_pair<<<BB * DM / 2, 512>>>(tr, ti);
        dim3 pg(8, OO / 128, BB);                 // f tiles 0..1023
        proj_kernel<<<pg, 256>>>(ti, biases[ti]);
        dim3 peg(BB, 4);
        proj_edge<<<peg, 128>>>(ti, biases[ti]);  // f = 1024
    }

    dim3 sg(8, 8, BB * HH);                       // l,s < 1024
    scores_kernel<<<sg, 256>>>(attn_ptr);
    scores_edge<<<BB * HH, 256>>>(attn_ptr);      // l=1024 row + s=1024 col

    softmax_kernel<<<BB * HH * FF, 256>>>(attn_ptr);

    dim3 cg(8, 1, BB * HH);                       // l < 1024
    ctx_kernel<<<cg, 256>>>(attn_ptr);
    ctx_edge<<<BB * HH, 64>>>(attn_ptr);          // l = 1024

    dim3 og(8, 8, BB);                            // f < 1024
    outproj_kernel<<<og, 256>>>(Wo, bo);
    dim3 oeg(BB, 8);
    outproj_edge<<<oeg, 128>>>(Wo, bo);           // f = 1024

    irfft_pair<<<BB * DM / 2, 512>>>(tr);

    dim3 tg2(DM / 32, LL / 32, BB);
    transpose_kernel<<<tg2, tb>>>(tr, out, DM, LL);
}

// round 14
// speedup vs baseline: 1.0426x; 1.0426x over previous
#include <cuda_runtime.h>
#include <math.h>

// Problem constants
#define BB 16
#define LL 2048
#define DM 512
#define FF 1025       // LL/2 + 1
#define FFP 1152      // padded F; pads stay zero (zero-init, never written)
#define HH 8
#define EE 64
#define OO 512        // HH*EE
#define NFFT 2048
#define KP 1024       // proj interleaved K = 2*DM

// ---------------- device scratch (static globals; zero-initialized) ----------------
__device__ float g_tr[(size_t)BB * DM * LL];                  // transpose scratch
__device__ float g_spec[3][(size_t)BB * KP * FFP];            // interleaved re/im rows (b, 2c+p, f)
__device__ float g_Wt[3][(size_t)KP * OO];                    // interleaved weights [k][o]
__device__ float g_w2[3][OO];
__device__ float g_qkT[2][(size_t)BB * OO * FFP];             // q,k heads (b, o, f)
__device__ float g_v[(size_t)BB * HH * FFP * EE];             // v heads (b,h,f,e)
__device__ float g_ctx[(size_t)BB * FFP * OO];                // (b, f, h*e)
__device__ float g_scores[(size_t)BB * HH * FF * FF];         // attn fallback
__device__ float g_yre[(size_t)BB * DM * FF];
__device__ float g_yim[(size_t)BB * DM * FF];

// ---------------- f32x2 packed helpers ----------------
__device__ __forceinline__ unsigned long long pk2(float x, float y) {
    unsigned long long r;
    asm("mov.b64 %0, {%1, %2};" : "=l"(r) : "f"(x), "f"(y));
    return r;
}
__device__ __forceinline__ void fma2(unsigned long long& d, unsigned long long a,
                                     unsigned long long b) {
    asm("fma.rn.f32x2 %0, %1, %2, %0;" : "+l"(d) : "l"(a), "l"(b));
}
__device__ __forceinline__ void upk2(unsigned long long v, float& x, float& y) {
    asm("mov.b64 {%0, %1}, %2;" : "=f"(x), "=f"(y) : "l"(v));
}

// ---------------- weight prep: interleave W0/W1 rows ----------------
__global__ void prep_w(const float* __restrict__ Wq, const float* __restrict__ Wk,
                       const float* __restrict__ Wv) {
    int idx = blockIdx.x * blockDim.x + threadIdx.x;
    if (idx >= 3 * KP * OO) return;
    int t = idx / (KP * OO);
    int r = idx % (KP * OO);
    int k = r / OO, o = r % OO;
    const float* W = (t == 0) ? Wq : (t == 1) ? Wk : Wv;
    g_Wt[t][(size_t)k * OO + o] = W[(o * DM + (k >> 1)) * 3 + (k & 1)];
}

__global__ void prep_w2(const float* __restrict__ Wq, const float* __restrict__ Wk,
                        const float* __restrict__ Wv) {
    int idx = blockIdx.x * blockDim.x + threadIdx.x;
    if (idx >= 3 * OO) return;
    int t = idx / OO;
    int o = idx % OO;
    const float* W = (t == 0) ? Wq : (t == 1) ? Wk : Wv;
    float s = 0.f;
    for (int c = 0; c < DM; ++c) s += W[(o * DM + c) * 3 + 2];
    g_w2[t][o] = s;
}

// ---------------- transpose (B, Ld, Cd) -> (B, Cd, Ld) ----------------
__global__ void transpose_kernel(const float* __restrict__ in, float* __restrict__ out,
                                 int Ld, int Cd) {
    __shared__ float tile[32][33];
    int b = blockIdx.z;
    int l0 = blockIdx.x * 32, c0 = blockIdx.y * 32;
    int tx = threadIdx.x, ty = threadIdx.y;
    #pragma unroll
    for (int i = 0; i < 32; i += 8) {
        int l = l0 + ty + i, c = c0 + tx;
        if (l < Ld && c < Cd) tile[ty + i][tx] = in[((size_t)b * Ld + l) * Cd + c];
    }
    __syncthreads();
    #pragma unroll
    for (int i = 0; i < 32; i += 8) {
        int c = c0 + ty + i, l = l0 + tx;
        if (c < Cd && l < Ld) out[((size_t)b * Cd + c) * Ld + l] = tile[tx][ty + i];
    }
}

// ---------------- forward rfft: two real channels per complex FFT ----------------
__global__ void rfft_pair(const float* __restrict__ x, int ti) {
    __shared__ float2 s[NFFT];
    int blk = blockIdx.x;
    int b = blk / (DM / 2);
    int p = (blk % (DM / 2)) * 2;
    const float* x0 = x + ((size_t)b * DM + p) * LL;
    int t = threadIdx.x;   // 512 threads
    for (int i = t; i < NFFT; i += 512) {
        int r = __brev((unsigned)i) >> 21;
        s[r] = make_float2(x0[i], x0[i + LL]);
    }
    __syncthreads();
    for (int sh = 0; sh < 11; ++sh) {
        int half = 1 << sh;
        for (int j = t; j < NFFT / 2; j += 512) {
            int pos = j & (half - 1);
            int base = ((j >> sh) << (sh + 1)) | pos;
            float ang = -3.14159265358979f * (float)pos / (float)half;
            float sw, cw; __sincosf(ang, &sw, &cw);
            float2 a = s[base], q2 = s[base + half];
            float tr = cw * q2.x - sw * q2.y;
            float tiy = cw * q2.y + sw * q2.x;
            s[base]        = make_float2(a.x + tr, a.y + tiy);
            s[base + half] = make_float2(a.x - tr, a.y - tiy);
        }
        __syncthreads();
    }
    float* sp = g_spec[ti];
    size_t o0 = ((size_t)b * KP + 2 * p) * FFP;
    for (int f = t; f <= NFFT / 2; f += 512) {
        float2 Zf = s[f];
        float2 Zn = s[(NFFT - f) & (NFFT - 1)];
        sp[o0 + f]            = 0.5f * (Zf.x + Zn.x);   // re ch p
        sp[o0 + FFP + f]      = 0.5f * (Zf.y - Zn.y);   // im ch p
        sp[o0 + 2 * FFP + f]  = 0.5f * (Zf.y + Zn.y);   // re ch p+1
        sp[o0 + 3 * FFP + f]  = 0.5f * (Zn.x - Zf.x);   // im ch p+1
    }
}

// ============ common 128x128 f32x2 inner product (16 k-steps) ============
#define GEMM_INNER_128(As, Bs, acc, ty, tx)                                          \
    _Pragma("unroll")                                                                \
    for (int kk = 0; kk < 16; ++kk) {                                                \
        float4 a0 = *(const float4*)&As[kk][(ty) * 4];                               \
        float4 a1 = *(const float4*)&As[kk][64 + (ty) * 4];                          \
        float4 b0 = *(const float4*)&Bs[kk][(tx) * 4];                               \
        float4 b1 = *(const float4*)&Bs[kk][64 + (tx) * 4];                          \
        unsigned long long bb0 = pk2(b0.x, b0.y), bb1 = pk2(b0.z, b0.w);             \
        unsigned long long bb2 = pk2(b1.x, b1.y), bb3 = pk2(b1.z, b1.w);             \
        float av[8] = {a0.x, a0.y, a0.z, a0.w, a1.x, a1.y, a1.z, a1.w};              \
        _Pragma("unroll")                                                            \
        for (int r = 0; r < 8; ++r) {                                                \
            unsigned long long ad = pk2(av[r], av[r]);                               \
            fma2(acc[r][0], ad, bb0); fma2(acc[r][1], ad, bb1);                      \
            fma2(acc[r][2], ad, bb2); fma2(acc[r][3], ad, bb3);                      \
        }                                                                            \
    }

// ---------------- projection GEMM: double-buffered, register-staged ----------------
__global__ __launch_bounds__(256, 2) void proj_kernel(int ti, const float* __restrict__ bias) {
    __shared__ float As[2][16][132], Bs[2][16][132];
    int b = blockIdx.z;
    int f0 = blockIdx.x * 128;
    int n0 = blockIdx.y * 128;
    int tid = threadIdx.x, ty = tid >> 4, tx = tid & 15;
    const float* sp = g_spec[ti];
    const float* Wt = g_Wt[ti];
    unsigned long long acc[8][4];
    #pragma unroll
    for (int r = 0; r < 8; ++r)
        #pragma unroll
        for (int c = 0; c < 4; ++c) acc[r][c] = 0ull;

    // prologue: k-tile 0 into buffer 0
    #pragma unroll
    for (int r = 0; r < 2; ++r) {
        int idx = tid + r * 256;
        int kk = idx >> 5, pos = (idx & 31) * 4;
        *(float4*)&As[0][kk][pos] = *(const float4*)&sp[((size_t)b * KP + kk) * FFP + f0 + pos];
        *(float4*)&Bs[0][kk][pos] = *(const float4*)&Wt[(size_t)kk * OO + n0 + pos];
    }
    __syncthreads();

    int cur = 0;
    for (int k0 = 0; k0 < KP; k0 += 16) {
        float4 sa[2], sb[2];
        bool more = (k0 + 16 < KP);
        if (more) {
            #pragma unroll
            for (int r = 0; r < 2; ++r) {
                int idx = tid + r * 256;
                int kk = idx >> 5, pos = (idx & 31) * 4;
                sa[r] = *(const float4*)&sp[((size_t)b * KP + k0 + 16 + kk) * FFP + f0 + pos];
                sb[r] = *(const float4*)&Wt[(size_t)(k0 + 16 + kk) * OO + n0 + pos];
            }
        }
        {
            const float (*Ac)[132] = As[cur];
            const float (*Bc)[132] = Bs[cur];
            GEMM_INNER_128(Ac, Bc, acc, ty, tx);
        }
        if (more) {
            int nxt = cur ^ 1;
            #pragma unroll
            for (int r = 0; r < 2; ++r) {
                int idx = tid + r * 256;
                int kk = idx >> 5, pos = (idx & 31) * 4;
                *(float4*)&As[nxt][kk][pos] = sa[r];
                *(float4*)&Bs[nxt][kk][pos] = sb[r];
            }
            __syncthreads();
            cur = nxt;
        }
    }

    float C[8][8];
    #pragma unroll
    for (int r = 0; r < 8; ++r)
        #pragma unroll
        for (int p2 = 0; p2 < 4; ++p2) upk2(acc[r][p2], C[r][p2 * 2], C[r][p2 * 2 + 1]);

    const float* w2 = g_w2[ti];
    #pragma unroll
    for (int r = 0; r < 8; ++r) {
        int f = f0 + ((r < 4) ? ty * 4 + r : 64 + ty * 4 + (r - 4));
        if (f >= FF) continue;
        float fr = (float)f * (1.0f / (float)NFFT);
        #pragma unroll
        for (int c = 0; c < 8; ++c) {
            int o = n0 + ((c < 4) ? tx * 4 + c : 64 + tx * 4 + (c - 4));
            float val = C[r][c] + fr * w2[o] + bias[o];
            if (ti < 2) {
                g_qkT[ti][((size_t)b * OO + o) * FFP + f] = val;
            } else {
                int h = o >> 6, e = o & 63;
                g_v[(((size_t)b * HH + h) * FFP + f) * EE + e] = val;
            }
        }
    }
}

// ---------------- scores: S = scale * Q K^T, double-buffered ----------------
__global__ __launch_bounds__(256, 2) void scores_kernel(float* __restrict__ attn) {
    __shared__ float As[2][16][132], Bs[2][16][132];
    int bh = blockIdx.z;
    int l0 = blockIdx.x * 128, s0 = blockIdx.y * 128;
    int tid = threadIdx.x, ty = tid >> 4, tx = tid & 15;
    const float* qb = g_qkT[0] + (size_t)bh * EE * FFP;
    const float* kb = g_qkT[1] + (size_t)bh * EE * FFP;
    unsigned long long acc[8][4];
    #pragma unroll
    for (int r = 0; r < 8; ++r)
        #pragma unroll
        for (int c = 0; c < 4; ++c) acc[r][c] = 0ull;

    #pragma unroll
    for (int r = 0; r < 2; ++r) {
        int idx = tid + r * 256;
        int kk = idx >> 5, pos = (idx & 31) * 4;
        *(float4*)&As[0][kk][pos] = *(const float4*)&qb[(size_t)kk * FFP + l0 + pos];
        *(float4*)&Bs[0][kk][pos] = *(const float4*)&kb[(size_t)kk * FFP + s0 + pos];
    }
    __syncthreads();

    int cur = 0;
    for (int k0 = 0; k0 < EE; k0 += 16) {
        float4 sa[2], sb[2];
        bool more = (k0 + 16 < EE);
        if (more) {
            #pragma unroll
            for (int r = 0; r < 2; ++r) {
                int idx = tid + r * 256;
                int kk = idx >> 5, pos = (idx & 31) * 4;
                sa[r] = *(const float4*)&qb[(size_t)(k0 + 16 + kk) * FFP + l0 + pos];
                sb[r] = *(const float4*)&kb[(size_t)(k0 + 16 + kk) * FFP + s0 + pos];
            }
        }
        {
            const float (*Ac)[132] = As[cur];
            const float (*Bc)[132] = Bs[cur];
            GEMM_INNER_128(Ac, Bc, acc, ty, tx);
        }
        if (more) {
            int nxt = cur ^ 1;
            #pragma unroll
            for (int r = 0; r < 2; ++r) {
                int idx = tid + r * 256;
                int kk = idx >> 5, pos = (idx & 31) * 4;
                *(float4*)&As[nxt][kk][pos] = sa[r];
                *(float4*)&Bs[nxt][kk][pos] = sb[r];
            }
            __syncthreads();
            cur = nxt;
        }
    }

    float C[8][8];
    #pragma unroll
    for (int r = 0; r < 8; ++r)
        #pragma unroll
        for (int p2 = 0; p2 < 4; ++p2) upk2(acc[r][p2], C[r][p2 * 2], C[r][p2 * 2 + 1]);

    const float scale = 0.125f;   // 1/sqrt(64)
    // Row stride FF=1025 is odd -> NO vector stores (misaligned-trap); scalar STG only.
    #pragma unroll
    for (int r = 0; r < 8; ++r) {
        int l = l0 + ((r < 4) ? ty * 4 + r : 64 + ty * 4 + (r - 4));
        if (l >= FF) continue;
        size_t row = ((size_t)bh * FF + l) * FF;
        #pragma unroll
        for (int c = 0; c < 8; ++c) {
            int s = s0 + ((c < 4) ? tx * 4 + c : 64 + tx * 4 + (c - 4));
            if (s < FF) attn[row + s] = C[r][c] * scale;
        }
    }
}

// ---------------- softmax over last axis, in place, warp-uniform MUFU skip ----------------
__global__ void softmax_kernel(float* __restrict__ A) {
    __shared__ float red[256];
    size_t row = blockIdx.x;
    float* p = A + row * FF;
    int t = threadIdx.x;
    float v[5];
    float mx = -1e30f;
    #pragma unroll
    for (int i = 0; i < 5; ++i) {
        int idx = t + i * 256;
        v[i] = (idx < FF) ? p[idx] : -1e30f;
        mx = fmaxf(mx, v[i]);
    }
    red[t] = mx; __syncthreads();
    for (int s = 128; s > 0; s >>= 1) {
        if (t < s) red[t] = fmaxf(red[t], red[t + s]);
        __syncthreads();
    }
    mx = red[0];
    __syncthreads();

    bool live = false;
    #pragma unroll
    for (int i = 0; i < 5; ++i) {
        v[i] -= mx;
        live = live || (v[i] > -80.0f);
    }
    float sum = 0.f;
    unsigned wm = __ballot_sync(0xffffffffu, live);
    if (wm != 0u) {
        #pragma unroll
        for (int i = 0; i < 5; ++i) {
            v[i] = __expf(v[i]);
            sum += v[i];
        }
    } else {
        #pragma unroll
        for (int i = 0; i < 5; ++i) v[i] = 0.f;
    }

    red[t] = sum; __syncthreads();
    for (int s = 128; s > 0; s >>= 1) {
        if (t < s) red[t] += red[t + s];
        __syncthreads();
    }
    float inv = 1.0f / red[0];
    #pragma unroll
    for (int i = 0; i < 5; ++i) {
        int idx = t + i * 256;
        if (idx < FF) p[idx] = v[i] * inv;
    }
}

// ---------------- ctx = attn @ V per (b,h); double-buffered ----------------
__global__ __launch_bounds__(256, 2) void ctx_kernel(const float* __restrict__ attn) {
    __shared__ float As[2][16][132], Bs[2][16][68];
    int bh = blockIdx.z;
    int l0 = blockIdx.x * 128;
    int tid = threadIdx.x, ty = tid >> 4, tx = tid & 15;
    const float* vb = g_v + (size_t)bh * FFP * EE;
    const float* Ab = attn + (size_t)bh * FF * FF;
    unsigned long long acc[8][2];
    #pragma unroll
    for (int r = 0; r < 8; ++r) { acc[r][0] = 0ull; acc[r][1] = 0ull; }

    // prologue: s-tile 0
    #pragma unroll
    for (int r = 0; r < 8; ++r) {
        int idx = tid + r * 256;
        int li = idx >> 4, ss = idx & 15;
        int l = l0 + li;
        As[0][ss][li] = (l < FF) ? Ab[(size_t)l * FF + ss] : 0.f;
    }
    {
        int kk = tid >> 4, pos = (tid & 15) * 4;
        *(float4*)&Bs[0][kk][pos] = *(const float4*)&vb[(size_t)kk * EE + pos];
    }
    __syncthreads();

    int cur = 0;
    for (int s0 = 0; s0 < 1040; s0 += 16) {
        float sa[8];
        float4 sbv;
        bool more = (s0 + 16 < 1040);
        if (more) {
            int sn = s0 + 16;
            #pragma unroll
            for (int r = 0; r < 8; ++r) {
                int idx = tid + r * 256;
                int li = idx >> 4, ss = idx & 15;
                int l = l0 + li, s = sn + ss;
                sa[r] = (l < FF && s < FF) ? Ab[(size_t)l * FF + s] : 0.f;
            }
            int kk = tid >> 4, pos = (tid & 15) * 4;
            sbv = *(const float4*)&vb[(size_t)(sn + kk) * EE + pos];
        }
        {
            const float (*Ac)[132] = As[cur];
            const float (*Bc)[68] = Bs[cur];
            #pragma unroll
            for (int kk = 0; kk < 16; ++kk) {
                float4 a0 = *(const float4*)&Ac[kk][ty * 4];
                float4 a1 = *(const float4*)&Ac[kk][64 + ty * 4];
                float4 b0 = *(const float4*)&Bc[kk][tx * 4];
                unsigned long long bb0 = pk2(b0.x, b0.y), bb1 = pk2(b0.z, b0.w);
                float av[8] = {a0.x, a0.y, a0.z, a0.w, a1.x, a1.y, a1.z, a1.w};
                #pragma unroll
                for (int r = 0; r < 8; ++r) {
                    unsigned long long ad = pk2(av[r], av[r]);
                    fma2(acc[r][0], ad, bb0);
                    fma2(acc[r][1], ad, bb1);
                }
            }
        }
        if (more) {
            int nxt = cur ^ 1;
            #pragma unroll
            for (int r = 0; r < 8; ++r) {
                int idx = tid + r * 256;
                int li = idx >> 4, ss = idx & 15;
                As[nxt][ss][li] = sa[r];
            }
            int kk = tid >> 4, pos = (tid & 15) * 4;
            *(float4*)&Bs[nxt][kk][pos] = sbv;
            __syncthreads();
            cur = nxt;
        }
    }

    int b = bh >> 3, h = bh & 7;
    #pragma unroll
    for (int r = 0; r < 8; ++r) {
        int l = l0 + ((r < 4) ? ty * 4 + r : 64 + ty * 4 + (r - 4));
        if (l >= FF) continue;
        float c0, c1, c2, c3;
        upk2(acc[r][0], c0, c1);
        upk2(acc[r][1], c2, c3);
        *(float4*)&g_ctx[((size_t)b * FFP + l) * OO + h * EE + tx * 4] =
            make_float4(c0, c1, c2, c3);
    }
}

// ---------------- output projection: double-buffered ----------------
__global__ __launch_bounds__(256, 2) void outproj_kernel(const float* __restrict__ Wo,
                                                         const float* __restrict__ bo) {
    __shared__ float As[2][16][132], Bs[2][16][132];
    int b = blockIdx.z;
    int m0 = blockIdx.x * 128;   // f tile
    int n0 = blockIdx.y * 128;   // output col tile (of 1024)
    int tid = threadIdx.x, ty = tid >> 4, tx = tid & 15;
    int mi = tid >> 1, cg = (tid & 1) * 8;
    unsigned long long acc[8][4];
    #pragma unroll
    for (int r = 0; r < 8; ++r)
        #pragma unroll
        for (int c = 0; c < 4; ++c) acc[r][c] = 0ull;

    // prologue: c-tile 0
    {
        const float* srcA = &g_ctx[((size_t)b * FFP + m0 + mi) * OO + cg];
        float4 t0 = *(const float4*)&srcA[0];
        float4 t1 = *(const float4*)&srcA[4];
        As[0][cg + 0][mi] = t0.x; As[0][cg + 1][mi] = t0.y;
        As[0][cg + 2][mi] = t0.z; As[0][cg + 3][mi] = t0.w;
        As[0][cg + 4][mi] = t1.x; As[0][cg + 5][mi] = t1.y;
        As[0][cg + 6][mi] = t1.z; As[0][cg + 7][mi] = t1.w;
        const float* srcB = &Wo[(size_t)(n0 + mi) * OO + cg];
        float4 u0 = *(const float4*)&srcB[0];
        float4 u1 = *(const float4*)&srcB[4];
        Bs[0][cg + 0][mi] = u0.x; Bs[0][cg + 1][mi] = u0.y;
        Bs[0][cg + 2][mi] = u0.z; Bs[0][cg + 3][mi] = u0.w;
        Bs[0][cg + 4][mi] = u1.x; Bs[0][cg + 5][mi] = u1.y;
        Bs[0][cg + 6][mi] = u1.z; Bs[0][cg + 7][mi] = u1.w;
    }
    __syncthreads();

    int cur = 0;
    for (int c0 = 0; c0 < OO; c0 += 16) {
        float4 ta0, ta1, tb0, tb1;
        bool more = (c0 + 16 < OO);
        if (more) {
            const float* srcA = &g_ctx[((size_t)b * FFP + m0 + mi) * OO + c0 + 16 + cg];
            ta0 = *(const float4*)&srcA[0];
            ta1 = *(const float4*)&srcA[4];
            const float* srcB = &Wo[(size_t)(n0 + mi) * OO + c0 + 16 + cg];
            tb0 = *(const float4*)&srcB[0];
            tb1 = *(const float4*)&srcB[4];
        }
        {
            const float (*Ac)[132] = As[cur];
            const float (*Bc)[132] = Bs[cur];
            GEMM_INNER_128(Ac, Bc, acc, ty, tx);
        }
        if (more) {
            int nxt = cur ^ 1;
            As[nxt][cg + 0][mi] = ta0.x; As[nxt][cg + 1][mi] = ta0.y;
            As[nxt][cg + 2][mi] = ta0.z; As[nxt][cg + 3][mi] = ta0.w;
            As[nxt][cg + 4][mi] = ta1.x; As[nxt][cg + 5][mi] = ta1.y;
            As[nxt][cg + 6][mi] = ta1.z; As[nxt][cg + 7][mi] = ta1.w;
            Bs[nxt][cg + 0][mi] = tb0.x; Bs[nxt][cg + 1][mi] = tb0.y;
            Bs[nxt][cg + 2][mi] = tb0.z; Bs[nxt][cg + 3][mi] = tb0.w;
            Bs[nxt][cg + 4][mi] = tb1.x; Bs[nxt][cg + 5][mi] = tb1.y;
            Bs[nxt][cg + 6][mi] = tb1.z; Bs[nxt][cg + 7][mi] = tb1.w;
            __syncthreads();
            cur = nxt;
        }
    }

    float C[8][8];
    #pragma unroll
    for (int r = 0; r < 8; ++r)
        #pragma unroll
        for (int p2 = 0; p2 < 4; ++p2) upk2(acc[r][p2], C[r][p2 * 2], C[r][p2 * 2 + 1]);

    #pragma unroll
    for (int r = 0; r < 8; ++r) {
        int f = m0 + ((r < 4) ? ty * 4 + r : 64 + ty * 4 + (r - 4));
        if (f >= FF) continue;
        #pragma unroll
        for (int c = 0; c < 8; ++c) {
            int jj = n0 + ((c < 4) ? tx * 4 + c : 64 + tx * 4 + (c - 4));
            float val = C[r][c] + bo[jj];
            int dd = jj >> 1;
            if (jj & 1) g_yim[((size_t)b * DM + dd) * FF + f] = val;
            else        g_yre[((size_t)b * DM + dd) * FF + f] = val;
        }
    }
}

// ---------------- inverse rfft (irfft discards imag of bins 0 and N/2) ----------------
__global__ void irfft_pair(float* __restrict__ xout) {
    __shared__ float2 s[NFFT];
    int blk = blockIdx.x;
    int b = blk / (DM / 2);
    int p = (blk % (DM / 2)) * 2;
    size_t i0 = ((size_t)b * DM + p) * FF;
    int t = threadIdx.x;  // 512
    for (int f = t; f <= NFFT / 2; f += 512) {
        float y0r = g_yre[i0 + f],      y0i = g_yim[i0 + f];
        float y1r = g_yre[i0 + FF + f], y1i = g_yim[i0 + FF + f];
        if (f == 0 || f == NFFT / 2) { y0i = 0.f; y1i = 0.f; }
        int r1 = __brev((unsigned)f) >> 21;
        s[r1] = make_float2(y0r - y1i, y0i + y1r);
        if (f > 0 && f < NFFT / 2) {
            int r2 = __brev((unsigned)(NFFT - f)) >> 21;
            s[r2] = make_float2(y0r + y1i, y1r - y0i);
        }
    }
    __syncthreads();
    for (int sh = 0; sh < 11; ++sh) {
        int half = 1 << sh;
        for (int j = t; j < NFFT / 2; j += 512) {
            int pos = j & (half - 1);
            int base = ((j >> sh) << (sh + 1)) | pos;
            float ang = 3.14159265358979f * (float)pos / (float)half;
            float sw, cw; __sincosf(ang, &sw, &cw);
            float2 a = s[base], q2 = s[base + half];
            float tr = cw * q2.x - sw * q2.y;
            float tiy = cw * q2.y + sw * q2.x;
            s[base]        = make_float2(a.x + tr, a.y + tiy);
            s[base + half] = make_float2(a.x - tr, a.y - tiy);
        }
        __syncthreads();
    }
    const float inv = 1.0f / (float)NFFT;
    size_t o0 = ((size_t)b * DM + p) * LL;
    for (int n = t; n < NFFT; n += 512) {
        xout[o0 + n]      = s[n].x * inv;
        xout[o0 + LL + n] = s[n].y * inv;
    }
}

// ---------------- launch ----------------
extern "C" void kernel_launch(void* const* d_in, const int* in_sizes, int n_in,
                              void* d_out, int out_size) {
    const float* q  = (const float*)d_in[0];
    const float* k  = (const float*)d_in[1];
    const float* v  = (const float*)d_in[2];
    const float* Wq = (const float*)d_in[3];
    const float* bq = (const float*)d_in[4];
    const float* Wk = (const float*)d_in[5];
    const float* bk = (const float*)d_in[6];
    const float* Wv = (const float*)d_in[7];
    const float* bv = (const float*)d_in[8];
    const float* Wo = (const float*)d_in[9];
    const float* bo = (const float*)d_in[10];
    float* out = (float*)d_out;

    const long long OUT_N  = (long long)BB * LL * DM;           // 16,777,216
    const long long ATTN_N = (long long)BB * HH * FF * FF;      // 134,480,000

    float* scores_dev = nullptr;
    cudaGetSymbolAddress((void**)&scores_dev, g_scores);
    float* tr = nullptr;
    cudaGetSymbolAddress((void**)&tr, g_tr);

    float* attn_ptr = scores_dev;
    if ((long long)out_size >= OUT_N + ATTN_N) attn_ptr = out + OUT_N;

    prep_w<<<(3 * KP * OO + 255) / 256, 256>>>(Wq, Wk, Wv);
    prep_w2<<<(3 * OO + 255) / 256, 256>>>(Wq, Wk, Wv);

    dim3 tb(32, 8);
    const float* ins[3]    = {q, k, v};
    const float* biases[3] = {bq, bk, bv};
    for (int ti = 0; ti < 3; ++ti) {
        dim3 tg(LL / 32, DM / 32, BB);
        transpose_kernel<<<tg, tb>>>(ins[ti], tr, LL, DM);
        rfft_pair<<<BB * DM / 2, 512>>>(tr, ti);
        dim3 pg(FFP / 128, OO / 128, BB);
        proj_kernel<<<pg, 256>>>(ti, biases[ti]);
    }

    dim3 sg(FFP / 128, FFP / 128, BB * HH);
    scores_kernel<<<sg, 256>>>(attn_ptr);

    softmax_kernel<<<BB * HH * FF, 256>>>(attn_ptr);

    dim3 cg(FFP / 128, 1, BB * HH);
    ctx_kernel<<<cg, 256>>>(attn_ptr);

    dim3 og(FFP / 128, 8, BB);
    outproj_kernel<<<og, 256>>>(Wo, bo);

    irfft_pair<<<BB * DM / 2, 512>>>(tr);

    dim3 tg2(DM / 32, LL / 32, BB);
    transpose_kernel<<<tg2, tb>>>(tr, out, DM, LL);
}

// round 15
// speedup vs baseline: 1.0782x; 1.0341x over previous
#include <cuda_runtime.h>
#include <math.h>

// Problem constants
#define BB 16
#define LL 2048
#define DM 512
#define FF 1025       // LL/2 + 1
#define FFP 1152      // padded F; pads stay zero (zero-init, never written)
#define HH 8
#define EE 64
#define OO 512        // HH*EE
#define NFFT 2048
#define KP 1024       // proj interleaved K = 2*DM

// ---------------- device scratch (static globals; zero-initialized) ----------------
__device__ float g_tr[(size_t)BB * DM * LL];                  // transpose scratch
__device__ float g_spec[3][(size_t)BB * KP * FFP];            // interleaved re/im rows (b, 2c+p, f)
__device__ float g_Wt[3][(size_t)KP * OO];                    // interleaved weights [k][o]
__device__ float g_w2[3][OO];
__device__ float g_qkT[2][(size_t)BB * OO * FFP];             // q,k heads (b, o, f)
__device__ float g_v[(size_t)BB * HH * FFP * EE];             // v heads (b,h,f,e)
__device__ float g_ctx[(size_t)BB * FFP * OO];                // (b, f, h*e)
__device__ float g_scores[(size_t)BB * HH * FF * FF];         // attn fallback
__device__ float g_yre[(size_t)BB * DM * FF];
__device__ float g_yim[(size_t)BB * DM * FF];

// ---------------- f32x2 packed helpers ----------------
__device__ __forceinline__ unsigned long long pk2(float x, float y) {
    unsigned long long r;
    asm("mov.b64 %0, {%1, %2};" : "=l"(r) : "f"(x), "f"(y));
    return r;
}
__device__ __forceinline__ void fma2(unsigned long long& d, unsigned long long a,
                                     unsigned long long b) {
    asm("fma.rn.f32x2 %0, %1, %2, %0;" : "+l"(d) : "l"(a), "l"(b));
}
__device__ __forceinline__ void upk2(unsigned long long v, float& x, float& y) {
    asm("mov.b64 {%0, %1}, %2;" : "=f"(x), "=f"(y) : "l"(v));
}

// ---------------- weight prep: interleave W0/W1 rows ----------------
__global__ void prep_w(const float* __restrict__ Wq, const float* __restrict__ Wk,
                       const float* __restrict__ Wv) {
    int idx = blockIdx.x * blockDim.x + threadIdx.x;
    if (idx >= 3 * KP * OO) return;
    int t = idx / (KP * OO);
    int r = idx % (KP * OO);
    int k = r / OO, o = r % OO;
    const float* W = (t == 0) ? Wq : (t == 1) ? Wk : Wv;
    g_Wt[t][(size_t)k * OO + o] = W[(o * DM + (k >> 1)) * 3 + (k & 1)];
}

__global__ void prep_w2(const float* __restrict__ Wq, const float* __restrict__ Wk,
                        const float* __restrict__ Wv) {
    int idx = blockIdx.x * blockDim.x + threadIdx.x;
    if (idx >= 3 * OO) return;
    int t = idx / OO;
    int o = idx % OO;
    const float* W = (t == 0) ? Wq : (t == 1) ? Wk : Wv;
    float s = 0.f;
    for (int c = 0; c < DM; ++c) s += W[(o * DM + c) * 3 + 2];
    g_w2[t][o] = s;
}

// ---------------- transpose (B, Ld, Cd) -> (B, Cd, Ld) ----------------
__global__ void transpose_kernel(const float* __restrict__ in, float* __restrict__ out,
                                 int Ld, int Cd) {
    __shared__ float tile[32][33];
    int b = blockIdx.z;
    int l0 = blockIdx.x * 32, c0 = blockIdx.y * 32;
    int tx = threadIdx.x, ty = threadIdx.y;
    #pragma unroll
    for (int i = 0; i < 32; i += 8) {
        int l = l0 + ty + i, c = c0 + tx;
        if (l < Ld && c < Cd) tile[ty + i][tx] = in[((size_t)b * Ld + l) * Cd + c];
    }
    __syncthreads();
    #pragma unroll
    for (int i = 0; i < 32; i += 8) {
        int c = c0 + ty + i, l = l0 + tx;
        if (c < Cd && l < Ld) out[((size_t)b * Cd + c) * Ld + l] = tile[tx][ty + i];
    }
}

// ---------------- forward rfft: two real channels per complex FFT ----------------
__global__ void rfft_pair(const float* __restrict__ x, int ti) {
    __shared__ float2 s[NFFT];
    int blk = blockIdx.x;
    int b = blk / (DM / 2);
    int p = (blk % (DM / 2)) * 2;
    const float* x0 = x + ((size_t)b * DM + p) * LL;
    int t = threadIdx.x;   // 512 threads
    for (int i = t; i < NFFT; i += 512) {
        int r = __brev((unsigned)i) >> 21;
        s[r] = make_float2(x0[i], x0[i + LL]);
    }
    __syncthreads();
    for (int sh = 0; sh < 11; ++sh) {
        int half = 1 << sh;
        for (int j = t; j < NFFT / 2; j += 512) {
            int pos = j & (half - 1);
            int base = ((j >> sh) << (sh + 1)) | pos;
            float ang = -3.14159265358979f * (float)pos / (float)half;
            float sw, cw; __sincosf(ang, &sw, &cw);
            float2 a = s[base], q2 = s[base + half];
            float tr = cw * q2.x - sw * q2.y;
            float tiy = cw * q2.y + sw * q2.x;
            s[base]        = make_float2(a.x + tr, a.y + tiy);
            s[base + half] = make_float2(a.x - tr, a.y - tiy);
        }
        __syncthreads();
    }
    float* sp = g_spec[ti];
    size_t o0 = ((size_t)b * KP + 2 * p) * FFP;
    for (int f = t; f <= NFFT / 2; f += 512) {
        float2 Zf = s[f];
        float2 Zn = s[(NFFT - f) & (NFFT - 1)];
        sp[o0 + f]            = 0.5f * (Zf.x + Zn.x);   // re ch p
        sp[o0 + FFP + f]      = 0.5f * (Zf.y - Zn.y);   // im ch p
        sp[o0 + 2 * FFP + f]  = 0.5f * (Zf.y + Zn.y);   // re ch p+1
        sp[o0 + 3 * FFP + f]  = 0.5f * (Zn.x - Zf.x);   // im ch p+1
    }
}

// ============ common 128x128 f32x2 inner product (16 k-steps) ============
#define GEMM_INNER_128(As, Bs, acc, ty, tx)                                          \
    _Pragma("unroll")                                                                \
    for (int kk = 0; kk < 16; ++kk) {                                                \
        float4 a0 = *(const float4*)&As[kk][(ty) * 4];                               \
        float4 a1 = *(const float4*)&As[kk][64 + (ty) * 4];                          \
        float4 b0 = *(const float4*)&Bs[kk][(tx) * 4];                               \
        float4 b1 = *(const float4*)&Bs[kk][64 + (tx) * 4];                          \
        unsigned long long bb0 = pk2(b0.x, b0.y), bb1 = pk2(b0.z, b0.w);             \
        unsigned long long bb2 = pk2(b1.x, b1.y), bb3 = pk2(b1.z, b1.w);             \
        float av[8] = {a0.x, a0.y, a0.z, a0.w, a1.x, a1.y, a1.z, a1.w};              \
        _Pragma("unroll")                                                            \
        for (int r = 0; r < 8; ++r) {                                                \
            unsigned long long ad = pk2(av[r], av[r]);                               \
            fma2(acc[r][0], ad, bb0); fma2(acc[r][1], ad, bb1);                      \
            fma2(acc[r][2], ad, bb2); fma2(acc[r][3], ad, bb3);                      \
        }                                                                            \
    }

// ---------------- projection GEMM (bx<8: 128-wide f tiles; bx==8: f=1024 edge) ----------------
__global__ __launch_bounds__(256, 2) void proj_kernel(int ti, const float* __restrict__ bias) {
    __shared__ float As[16][132], Bs[16][132];
    int b = blockIdx.z;
    int n0 = blockIdx.y * 128;
    int tid = threadIdx.x, ty = tid >> 4, tx = tid & 15;
    const float* sp = g_spec[ti];
    const float* Wt = g_Wt[ti];

    if (blockIdx.x == 8) {
        // edge: single f = 1024 column, whole block cooperates
        float* sc  = &As[0][0];    // 1024 floats (fits in As)
        float* red = &Bs[0][0];    // 256 floats
        for (int k = tid; k < KP; k += 256)
            sc[k] = sp[((size_t)b * KP + k) * FFP + 1024];
        __syncthreads();
        int o = n0 + (tid & 127);
        int kh = tid >> 7;                 // 0/1 split of K
        float a0 = 0.f, a1 = 0.f;
        int kbeg = kh * 512;
        for (int k = kbeg; k < kbeg + 512; k += 2) {
            a0 += sc[k] * Wt[(size_t)k * OO + o];
            a1 += sc[k + 1] * Wt[(size_t)(k + 1) * OO + o];
        }
        red[tid] = a0 + a1;
        __syncthreads();
        if (kh == 0) {
            float val = red[tid] + red[tid + 128] + 0.5f * g_w2[ti][o] + bias[o];
            if (ti < 2) g_qkT[ti][((size_t)b * OO + o) * FFP + 1024] = val;
            else {
                int h = o >> 6, e = o & 63;
                g_v[(((size_t)b * HH + h) * FFP + 1024) * EE + e] = val;
            }
        }
        return;
    }

    int f0 = blockIdx.x * 128;
    unsigned long long acc[8][4];
    #pragma unroll
    for (int r = 0; r < 8; ++r)
        #pragma unroll
        for (int c = 0; c < 4; ++c) acc[r][c] = 0ull;

    for (int k0 = 0; k0 < KP; k0 += 16) {
        #pragma unroll
        for (int r = 0; r < 2; ++r) {
            int idx = tid + r * 256;
            int kk = idx >> 5, pos = (idx & 31) * 4;
            *(float4*)&As[kk][pos] =
                *(const float4*)&sp[((size_t)b * KP + k0 + kk) * FFP + f0 + pos];
            *(float4*)&Bs[kk][pos] =
                *(const float4*)&Wt[(size_t)(k0 + kk) * OO + n0 + pos];
        }
        __syncthreads();
        GEMM_INNER_128(As, Bs, acc, ty, tx);
        __syncthreads();
    }

    float C[8][8];
    #pragma unroll
    for (int r = 0; r < 8; ++r)
        #pragma unroll
        for (int p2 = 0; p2 < 4; ++p2) upk2(acc[r][p2], C[r][p2 * 2], C[r][p2 * 2 + 1]);

    const float* w2 = g_w2[ti];
    #pragma unroll
    for (int r = 0; r < 8; ++r) {
        int f = f0 + ((r < 4) ? ty * 4 + r : 64 + ty * 4 + (r - 4));   // always < 1024
        float fr = (float)f * (1.0f / (float)NFFT);
        #pragma unroll
        for (int c = 0; c < 8; ++c) {
            int o = n0 + ((c < 4) ? tx * 4 + c : 64 + tx * 4 + (c - 4));
            float val = C[r][c] + fr * w2[o] + bias[o];
            if (ti < 2) {
                g_qkT[ti][((size_t)b * OO + o) * FFP + f] = val;
            } else {
                int h = o >> 6, e = o & 63;
                g_v[(((size_t)b * HH + h) * FFP + f) * EE + e] = val;
            }
        }
    }
}

// ---------------- scores (bx,by<8: 128x128 tiles; bx==8: l=1024 row; by==8: s=1024 col) ----------------
__global__ __launch_bounds__(256, 2) void scores_kernel(float* __restrict__ attn) {
    __shared__ float As[16][132], Bs[16][132];
    int bh = blockIdx.z;
    int tid = threadIdx.x, ty = tid >> 4, tx = tid & 15;
    const float* qb = g_qkT[0] + (size_t)bh * EE * FFP;
    const float* kb = g_qkT[1] + (size_t)bh * EE * FFP;
    const float scale = 0.125f;   // 1/sqrt(64)

    if (blockIdx.x == 8) {
        // edge: l = 1024 row, s range [s0, min(s0+128, FF))
        float* qe = &As[0][0];
        if (tid < 64) qe[tid] = qb[(size_t)tid * FFP + 1024];
        __syncthreads();
        int s0 = blockIdx.y * 128;
        int smax = (s0 + 128 < FF) ? s0 + 128 : FF;
        for (int s = s0 + tid; s < smax; s += 256) {
            float a = 0.f;
            #pragma unroll 8
            for (int e = 0; e < 64; ++e) a += qe[e] * kb[(size_t)e * FFP + s];
            attn[((size_t)bh * FF + 1024) * FF + s] = a * scale;
        }
        return;
    }
    if (blockIdx.y == 8) {
        // edge: s = 1024 column, l range [l0, l0+128)
        float* ke = &As[0][0];
        if (tid < 64) ke[tid] = kb[(size_t)tid * FFP + 1024];
        __syncthreads();
        int l0 = blockIdx.x * 128;
        for (int l = l0 + tid; l < l0 + 128; l += 256) {
            float a = 0.f;
            #pragma unroll 8
            for (int e = 0; e < 64; ++e) a += qb[(size_t)e * FFP + l] * ke[e];
            attn[((size_t)bh * FF + l) * FF + 1024] = a * scale;
        }
        return;
    }

    int l0 = blockIdx.x * 128, s0 = blockIdx.y * 128;
    unsigned long long acc[8][4];
    #pragma unroll
    for (int r = 0; r < 8; ++r)
        #pragma unroll
        for (int c = 0; c < 4; ++c) acc[r][c] = 0ull;

    for (int k0 = 0; k0 < EE; k0 += 16) {
        #pragma unroll
        for (int r = 0; r < 2; ++r) {
            int idx = tid + r * 256;
            int kk = idx >> 5, pos = (idx & 31) * 4;
            *(float4*)&As[kk][pos] = *(const float4*)&qb[(size_t)(k0 + kk) * FFP + l0 + pos];
            *(float4*)&Bs[kk][pos] = *(const float4*)&kb[(size_t)(k0 + kk) * FFP + s0 + pos];
        }
        __syncthreads();
        GEMM_INNER_128(As, Bs, acc, ty, tx);
        __syncthreads();
    }

    float C[8][8];
    #pragma unroll
    for (int r = 0; r < 8; ++r)
        #pragma unroll
        for (int p2 = 0; p2 < 4; ++p2) upk2(acc[r][p2], C[r][p2 * 2], C[r][p2 * 2 + 1]);

    // Row stride FF=1025 is odd -> scalar STG only (vector stores would trap).
    #pragma unroll
    for (int r = 0; r < 8; ++r) {
        int l = l0 + ((r < 4) ? ty * 4 + r : 64 + ty * 4 + (r - 4));   // < 1024
        size_t row = ((size_t)bh * FF + l) * FF;
        #pragma unroll
        for (int c = 0; c < 8; ++c) {
            int s = s0 + ((c < 4) ? tx * 4 + c : 64 + tx * 4 + (c - 4));  // < 1024
            attn[row + s] = C[r][c] * scale;
        }
    }
}

// ---------------- softmax over last axis, in place, warp-uniform MUFU skip ----------------
__global__ void softmax_kernel(float* __restrict__ A) {
    __shared__ float red[256];
    size_t row = blockIdx.x;
    float* p = A + row * FF;
    int t = threadIdx.x;
    float v[5];
    float mx = -1e30f;
    #pragma unroll
    for (int i = 0; i < 5; ++i) {
        int idx = t + i * 256;
        v[i] = (idx < FF) ? p[idx] : -1e30f;
        mx = fmaxf(mx, v[i]);
    }
    red[t] = mx; __syncthreads();
    for (int s = 128; s > 0; s >>= 1) {
        if (t < s) red[t] = fmaxf(red[t], red[t + s]);
        __syncthreads();
    }
    mx = red[0];
    __syncthreads();

    bool live = false;
    #pragma unroll
    for (int i = 0; i < 5; ++i) {
        v[i] -= mx;
        live = live || (v[i] > -80.0f);
    }
    float sum = 0.f;
    unsigned wm = __ballot_sync(0xffffffffu, live);
    if (wm != 0u) {
        #pragma unroll
        for (int i = 0; i < 5; ++i) {
            v[i] = __expf(v[i]);
            sum += v[i];
        }
    } else {
        #pragma unroll
        for (int i = 0; i < 5; ++i) v[i] = 0.f;
    }

    red[t] = sum; __syncthreads();
    for (int s = 128; s > 0; s >>= 1) {
        if (t < s) red[t] += red[t + s];
        __syncthreads();
    }
    float inv = 1.0f / red[0];
    #pragma unroll
    for (int i = 0; i < 5; ++i) {
        int idx = t + i * 256;
        if (idx < FF) p[idx] = v[i] * inv;
    }
}

// ---------------- ctx = attn @ V per (b,h) (bx<8: 128-row tiles; bx==8: l=1024) ----------------
__global__ __launch_bounds__(256, 2) void ctx_kernel(const float* __restrict__ attn) {
    __shared__ float As[16][132], Bs[16][68];
    int bh = blockIdx.z;
    int tid = threadIdx.x, ty = tid >> 4, tx = tid & 15;
    const float* vb = g_v + (size_t)bh * FFP * EE;
    const float* Ab = attn + (size_t)bh * FF * FF;
    int b = bh >> 3, h = bh & 7;

    if (blockIdx.x == 8) {
        // edge: single l = 1024 row
        float* red = &As[0][0];
        int e = tid & 63, sq = tid >> 6;    // 4-way split of s
        const float* arow = Ab + (size_t)1024 * FF;
        float a = 0.f;
        int sbeg = sq * 257;
        int send = (sbeg + 257 < FF) ? sbeg + 257 : FF;
        for (int s = sbeg; s < send; ++s)
            a += arow[s] * vb[(size_t)s * EE + e];
        red[tid] = a;
        __syncthreads();
        if (sq == 0) {
            float val = red[e] + red[e + 64] + red[e + 128] + red[e + 192];
            g_ctx[((size_t)b * FFP + 1024) * OO + h * EE + e] = val;
        }
        return;
    }

    int l0 = blockIdx.x * 128;
    unsigned long long acc[8][2];
    #pragma unroll
    for (int r = 0; r < 8; ++r) { acc[r][0] = 0ull; acc[r][1] = 0ull; }

    for (int s0 = 0; s0 < 1040; s0 += 16) {
        #pragma unroll
        for (int r = 0; r < 8; ++r) {
            int idx = tid + r * 256;
            int li = idx >> 4, ss = idx & 15;
            int l = l0 + li, s = s0 + ss;
            As[ss][li] = (s < FF) ? Ab[(size_t)l * FF + s] : 0.f;
        }
        {
            int kk = tid >> 4, pos = (tid & 15) * 4;
            *(float4*)&Bs[kk][pos] = *(const float4*)&vb[(size_t)(s0 + kk) * EE + pos];
        }
        __syncthreads();
        #pragma unroll
        for (int kk = 0; kk < 16; ++kk) {
            float4 a0 = *(const float4*)&As[kk][ty * 4];
            float4 a1 = *(const float4*)&As[kk][64 + ty * 4];
            float4 b0 = *(const float4*)&Bs[kk][tx * 4];
            unsigned long long bb0 = pk2(b0.x, b0.y), bb1 = pk2(b0.z, b0.w);
            float av[8] = {a0.x, a0.y, a0.z, a0.w, a1.x, a1.y, a1.z, a1.w};
            #pragma unroll
            for (int r = 0; r < 8; ++r) {
                unsigned long long ad = pk2(av[r], av[r]);
                fma2(acc[r][0], ad, bb0);
                fma2(acc[r][1], ad, bb1);
            }
        }
        __syncthreads();
    }

    #pragma unroll
    for (int r = 0; r < 8; ++r) {
        int l = l0 + ((r < 4) ? ty * 4 + r : 64 + ty * 4 + (r - 4));   // < 1024
        float c0, c1, c2, c3;
        upk2(acc[r][0], c0, c1);
        upk2(acc[r][1], c2, c3);
        *(float4*)&g_ctx[((size_t)b * FFP + l) * OO + h * EE + tx * 4] =
            make_float4(c0, c1, c2, c3);
    }
}

// ---------------- output projection (bx<8: 128-wide f tiles; bx==8: f=1024 edge) ----------------
__global__ __launch_bounds__(256, 2) void outproj_kernel(const float* __restrict__ Wo,
                                                         const float* __restrict__ bo) {
    __shared__ float As[16][132], Bs[16][132];
    int b = blockIdx.z;
    int n0 = blockIdx.y * 128;   // output col tile (of 1024)
    int tid = threadIdx.x, ty = tid >> 4, tx = tid & 15;

    if (blockIdx.x == 8) {
        // edge: single f = 1024 column
        float* cs  = &As[0][0];    // 512 floats
        float* red = &Bs[0][0];    // 256 floats
        for (int c = tid; c < OO; c += 256)
            cs[c] = g_ctx[((size_t)b * FFP + 1024) * OO + c];
        __syncthreads();
        int jj = n0 + (tid & 127);
        int kh = tid >> 7;
        const float* wrow = Wo + (size_t)jj * OO;
        float a0 = 0.f, a1 = 0.f;
        int cbeg = kh * 256;
        for (int c = cbeg; c < cbeg + 256; c += 2) {
            a0 += cs[c] * wrow[c];
            a1 += cs[c + 1] * wrow[c + 1];
        }
        red[tid] = a0 + a1;
        __syncthreads();
        if (kh == 0) {
            float val = red[tid] + red[tid + 128] + bo[jj];
            int dd = jj >> 1;
            if (jj & 1) g_yim[((size_t)b * DM + dd) * FF + 1024] = val;
            else        g_yre[((size_t)b * DM + dd) * FF + 1024] = val;
        }
        return;
    }

    int m0 = blockIdx.x * 128;   // f tile
    unsigned long long acc[8][4];
    #pragma unroll
    for (int r = 0; r < 8; ++r)
        #pragma unroll
        for (int c = 0; c < 4; ++c) acc[r][c] = 0ull;

    for (int c0 = 0; c0 < OO; c0 += 16) {
        int mi = tid >> 1, cg = (tid & 1) * 8;
        {
            const float* src = &g_ctx[((size_t)b * FFP + m0 + mi) * OO + c0 + cg];
            float4 t0 = *(const float4*)&src[0];
            float4 t1 = *(const float4*)&src[4];
            As[cg + 0][mi] = t0.x; As[cg + 1][mi] = t0.y;
            As[cg + 2][mi] = t0.z; As[cg + 3][mi] = t0.w;
            As[cg + 4][mi] = t1.x; As[cg + 5][mi] = t1.y;
            As[cg + 6][mi] = t1.z; As[cg + 7][mi] = t1.w;
        }
        {
            const float* src = &Wo[(size_t)(n0 + mi) * OO + c0 + cg];
            float4 t0 = *(const float4*)&src[0];
            float4 t1 = *(const float4*)&src[4];
            Bs[cg + 0][mi] = t0.x; Bs[cg + 1][mi] = t0.y;
            Bs[cg + 2][mi] = t0.z; Bs[cg + 3][mi] = t0.w;
            Bs[cg + 4][mi] = t1.x; Bs[cg + 5][mi] = t1.y;
            Bs[cg + 6][mi] = t1.z; Bs[cg + 7][mi] = t1.w;
        }
        __syncthreads();
        GEMM_INNER_128(As, Bs, acc, ty, tx);
        __syncthreads();
    }

    float C[8][8];
    #pragma unroll
    for (int r = 0; r < 8; ++r)
        #pragma unroll
        for (int p2 = 0; p2 < 4; ++p2) upk2(acc[r][p2], C[r][p2 * 2], C[r][p2 * 2 + 1]);

    #pragma unroll
    for (int r = 0; r < 8; ++r) {
        int f = m0 + ((r < 4) ? ty * 4 + r : 64 + ty * 4 + (r - 4));   // < 1024
        #pragma unroll
        for (int c = 0; c < 8; ++c) {
            int jj = n0 + ((c < 4) ? tx * 4 + c : 64 + tx * 4 + (c - 4));
            float val = C[r][c] + bo[jj];
            int dd = jj >> 1;
            if (jj & 1) g_yim[((size_t)b * DM + dd) * FF + f] = val;
            else        g_yre[((size_t)b * DM + dd) * FF + f] = val;
        }
    }
}

// ---------------- inverse rfft (irfft discards imag of bins 0 and N/2) ----------------
__global__ void irfft_pair(float* __restrict__ xout) {
    __shared__ float2 s[NFFT];
    int blk = blockIdx.x;
    int b = blk / (DM / 2);
    int p = (blk % (DM / 2)) * 2;
    size_t i0 = ((size_t)b * DM + p) * FF;
    int t = threadIdx.x;  // 512
    for (int f = t; f <= NFFT / 2; f += 512) {
        float y0r = g_yre[i0 + f],      y0i = g_yim[i0 + f];
        float y1r = g_yre[i0 + FF + f], y1i = g_yim[i0 + FF + f];
        if (f == 0 || f == NFFT / 2) { y0i = 0.f; y1i = 0.f; }
        int r1 = __brev((unsigned)f) >> 21;
        s[r1] = make_float2(y0r - y1i, y0i + y1r);
        if (f > 0 && f < NFFT / 2) {
            int r2 = __brev((unsigned)(NFFT - f)) >> 21;
            s[r2] = make_float2(y0r + y1i, y1r - y0i);
        }
    }
    __syncthreads();
    for (int sh = 0; sh < 11; ++sh) {
        int half = 1 << sh;
        for (int j = t; j < NFFT / 2; j += 512) {
            int pos = j & (half - 1);
            int base = ((j >> sh) << (sh + 1)) | pos;
            float ang = 3.14159265358979f * (float)pos / (float)half;
            float sw, cw; __sincosf(ang, &sw, &cw);
            float2 a = s[base], q2 = s[base + half];
            float tr = cw * q2.x - sw * q2.y;
            float tiy = cw * q2.y + sw * q2.x;
            s[base]        = make_float2(a.x + tr, a.y + tiy);
            s[base + half] = make_float2(a.x - tr, a.y - tiy);
        }
        __syncthreads();
    }
    const float inv = 1.0f / (float)NFFT;
    size_t o0 = ((size_t)b * DM + p) * LL;
    for (int n = t; n < NFFT; n += 512) {
        xout[o0 + n]      = s[n].x * inv;
        xout[o0 + LL + n] = s[n].y * inv;
    }
}

// ---------------- launch ----------------
extern "C" void kernel_launch(void* const* d_in, const int* in_sizes, int n_in,
                              void* d_out, int out_size) {
    const float* q  = (const float*)d_in[0];
    const float* k  = (const float*)d_in[1];
    const float* v  = (const float*)d_in[2];
    const float* Wq = (const float*)d_in[3];
    const float* bq = (const float*)d_in[4];
    const float* Wk = (const float*)d_in[5];
    const float* bk = (const float*)d_in[6];
    const float* Wv = (const float*)d_in[7];
    const float* bv = (const float*)d_in[8];
    const float* Wo = (const float*)d_in[9];
    const float* bo = (const float*)d_in[10];
    float* out = (float*)d_out;

    const long long OUT_N  = (long long)BB * LL * DM;           // 16,777,216
    const long long ATTN_N = (long long)BB * HH * FF * FF;      // 134,480,000

    float* scores_dev = nullptr;
    cudaGetSymbolAddress((void**)&scores_dev, g_scores);
    float* tr = nullptr;
    cudaGetSymbolAddress((void**)&tr, g_tr);

    float* attn_ptr = scores_dev;
    if ((long long)out_size >= OUT_N + ATTN_N) attn_ptr = out + OUT_N;

    prep_w<<<(3 * KP * OO + 255) / 256, 256>>>(Wq, Wk, Wv);
    prep_w2<<<(3 * OO + 255) / 256, 256>>>(Wq, Wk, Wv);

    dim3 tb(32, 8);
    const float* ins[3]    = {q, k, v};
    const float* biases[3] = {bq, bk, bv};
    for (int ti = 0; ti < 3; ++ti) {
        dim3 tg(LL / 32, DM / 32, BB);
        transpose_kernel<<<tg, tb>>>(ins[ti], tr, LL, DM);
        rfft_pair<<<BB * DM / 2, 512>>>(tr, ti);
        dim3 pg(9, OO / 128, BB);            // bx==8 handles f=1024 edge in-kernel
        proj_kernel<<<pg, 256>>>(ti, biases[ti]);
    }

    dim3 sg(9, 9, BB * HH);                  // bx==8 / by==8 handle l/s=1024 edges
    scores_kernel<<<sg, 256>>>(attn_ptr);

    softmax_kernel<<<BB * HH * FF, 256>>>(attn_ptr);

    dim3 cg(9, 1, BB * HH);                  // bx==8 handles l=1024 edge
    ctx_kernel<<<cg, 256>>>(attn_ptr);

    dim3 og(9, 8, BB);                       // bx==8 handles f=1024 edge
    outproj_kernel<<<og, 256>>>(Wo, bo);

    irfft_pair<<<BB * DM / 2, 512>>>(tr);

    dim3 tg2(DM / 32, LL / 32, BB);
    transpose_kernel<<<tg2, tb>>>(tr, out, DM, LL);
}